// round 15
// baseline (speedup 1.0000x reference)
#include <cuda_runtime.h>
#include <cuda_bf16.h>
#include <cuda_fp16.h>
#include <cstdint>

// ---------------------------------------------------------------------------
// MiddleLayerDecoder — round 14: R12 (K32 both arms) + 3-stage cp.async ring
// on the fp16 arm only (NSTG = IS16 ? 3 : 2); bf16 arm codegen unchanged.
// ---------------------------------------------------------------------------

#define N_NODES 50000
#define KPTS 8
#define M_PTS (N_NODES * KPTS)

// ---- activation planes ----
__device__ __align__(16) __nv_bfloat16 g_xhi[(size_t)N_NODES * 256];
__device__ __align__(16) __nv_bfloat16 g_xlo[(size_t)N_NODES * 256];
__device__ __align__(16) __nv_bfloat16 g_h1hi[(size_t)N_NODES * 256];
__device__ __align__(16) __nv_bfloat16 g_h1lo[(size_t)N_NODES * 256];
__device__ __align__(16) __nv_bfloat16 g_h2hi[(size_t)N_NODES * 128];
__device__ __align__(16) __nv_bfloat16 g_h2lo[(size_t)N_NODES * 128];
__device__ __align__(16) __nv_bfloat16 g_fhi[(size_t)N_NODES * 64];
__device__ __align__(16) __nv_bfloat16 g_flo[(size_t)N_NODES * 64];
__device__ __align__(16) unsigned short g_p1hi[(size_t)M_PTS * 256];  // fp16 plane
// fp32 scratch
__device__ float g_T[(size_t)N_NODES * 256];
__device__ float g_A[(size_t)N_NODES * 256];
// weight planes pool (bf16 or fp16 bits)
__device__ __align__(16) unsigned short g_whi[335872];
__device__ __align__(16) unsigned short g_wlo[335872];

// pool map
#define OFF_WG0A 0        // 256 x 512 (Wg0 | W0a), bf16
#define OFF_WG1  131072   // 256 x 128, bf16
#define OFF_WG2  163840   // 128 x 128, bf16
#define OFF_WDEC 180224   //  64 x 128, bf16
#define OFF_W0B  188416   //  64 x 256, bf16
#define OFF_W1   204800   // 256 x 256, fp16
#define OFF_W2   270336   // 256 x 256, fp16

__device__ __forceinline__ uint32_t smem_u32(const void* p) {
    uint32_t a;
    asm("{ .reg .u64 t; cvta.to.shared.u64 t, %1; cvt.u32.u64 %0, t; }" : "=r"(a) : "l"(p));
    return a;
}
__device__ __forceinline__ uint32_t pack2(__nv_bfloat16 a, __nv_bfloat16 b) {
    return (uint32_t)__bfloat16_as_ushort(a) | ((uint32_t)__bfloat16_as_ushort(b) << 16);
}
__device__ __forceinline__ uint32_t pack2h(__half a, __half b) {
    return (uint32_t)__half_as_ushort(a) | ((uint32_t)__half_as_ushort(b) << 16);
}
__device__ __forceinline__ void ldm_x4(uint32_t* r, uint32_t addr) {
    asm volatile("ldmatrix.sync.aligned.m8n8.x4.shared.b16 {%0,%1,%2,%3}, [%4];"
                 : "=r"(r[0]), "=r"(r[1]), "=r"(r[2]), "=r"(r[3]) : "r"(addr));
}
__device__ __forceinline__ void ldm_x4t(uint32_t* r, uint32_t addr) {
    asm volatile("ldmatrix.sync.aligned.m8n8.x4.trans.shared.b16 {%0,%1,%2,%3}, [%4];"
                 : "=r"(r[0]), "=r"(r[1]), "=r"(r[2]), "=r"(r[3]) : "r"(addr));
}
__device__ __forceinline__ void mma16816(float* c, const uint32_t* a, const uint32_t* b) {
    asm volatile("mma.sync.aligned.m16n8k16.row.col.f32.bf16.bf16.f32 "
                 "{%0,%1,%2,%3}, {%4,%5,%6,%7}, {%8,%9}, {%0,%1,%2,%3};"
                 : "+f"(c[0]), "+f"(c[1]), "+f"(c[2]), "+f"(c[3])
                 : "r"(a[0]), "r"(a[1]), "r"(a[2]), "r"(a[3]), "r"(b[0]), "r"(b[1]));
}
__device__ __forceinline__ void mma16816h(float* c, const uint32_t* a, const uint32_t* b) {
    asm volatile("mma.sync.aligned.m16n8k16.row.col.f32.f16.f16.f32 "
                 "{%0,%1,%2,%3}, {%4,%5,%6,%7}, {%8,%9}, {%0,%1,%2,%3};"
                 : "+f"(c[0]), "+f"(c[1]), "+f"(c[2]), "+f"(c[3])
                 : "r"(a[0]), "r"(a[1]), "r"(a[2]), "r"(a[3]), "r"(b[0]), "r"(b[1]));
}
__device__ __forceinline__ void cp16(uint32_t dst, const void* src, int sz) {
    asm volatile("cp.async.cg.shared.global [%0], [%1], 16, %2;"
                 :: "r"(dst), "l"(src), "r"(sz) : "memory");
}
__device__ __forceinline__ void cp_commit() {
    asm volatile("cp.async.commit_group;" ::: "memory");
}
template <int NN>
__device__ __forceinline__ void cp_wait() {
    asm volatile("cp.async.wait_group %0;" :: "n"(NN) : "memory");
}

// stage layouts (both arms K32 chunks)
#define ASTRIDE 80
#define BSTRIDE 272
#define SA_HI 0
// bf16 (3-term): A hi/lo + B hi/lo
#define SA_LO_B 10240
#define SB_HI_B 20480
#define STAGE_B 37888
// fp16 (2-term): A hi only + B hi/lo
#define SB_HI_H 10240
#define STAGE_H 27648
#define SB_LO_DELTA 8704   // 32*272
#define SMEM_DYN_B (STAGE_B * 2)
#define SMEM_DYN_H (STAGE_H * 3)

// MODE 0: A from pre-split planes (cp.async); MODE 1: A built on the fly (h0)
// NSPLIT>0: cols >= NSPLIT -> OutF fp32 + bias2, no relu
// IS16: fp16 2-term (A single plane), 3-stage ring; else bf16 3-term, 2-stage
template <int MODE, int NSPLIT, int IS16>
__global__ __launch_bounds__(256, 2)
void gemm_mma(const unsigned short* __restrict__ Ahi,
              const unsigned short* __restrict__ Alo,
              const unsigned short* __restrict__ Bhi,
              const unsigned short* __restrict__ Blo,
              const float* __restrict__ bias, const float* __restrict__ bias2,
              const float* __restrict__ Cin,
              const float* __restrict__ Anode, const float* __restrict__ rel,
              const float* __restrict__ W0c3,
              float* __restrict__ OutF,
              unsigned short* __restrict__ OutHi, unsigned short* __restrict__ OutLo,
              int M, int K, int Np, int realN, int ldc, int doRelu)
{
    constexpr uint32_t SBH  = IS16 ? SB_HI_H : SB_HI_B;
    constexpr uint32_t STB  = IS16 ? STAGE_H : STAGE_B;
    constexpr int      NSTG = IS16 ? 3 : 2;

    extern __shared__ __align__(128) char smem[];
    const uint32_t sb = smem_u32(smem);
    const int tid = threadIdx.x, lane = tid & 31, wid = tid >> 5;
    const int warpM = (wid & 1) * 64;
    const int warpN = (wid >> 1) * 32;
    const long m0 = (long)blockIdx.y * 128;
    const int  n0 = blockIdx.x * 128;
    const int  nc = K >> 5;

    auto issue_chunk = [&](int c) {
        const uint32_t st = sb + (uint32_t)(c % NSTG) * STB;
        const int k0 = c << 5;
        if (MODE == 0) {
#pragma unroll
            for (int t = 0; t < (IS16 ? 2 : 4); t++) {
                const int gi = tid + t * 256;
                const int pl = gi >> 9, idx = gi & 511;
                const int row = idx >> 2, q = idx & 3;
                const long gm = m0 + row;
                const unsigned short* src =
                    (pl ? Alo : Ahi) + (gm < M ? gm : 0) * (long)K + k0 + q * 8;
                const uint32_t dst = st + (pl ? SA_LO_B : SA_HI) + row * ASTRIDE + q * 16;
                cp16(dst, src, gm < M ? 16 : 0);
            }
        }
#pragma unroll
        for (int t = 0; t < 4; t++) {
            const int gi = tid + t * 256;
            const int pl = gi >> 9, idx = gi & 511;
            const int row = idx >> 4, q = idx & 15;
            const unsigned short* src =
                (pl ? Blo : Bhi) + (long)(k0 + row) * Np + n0 + q * 8;
            const uint32_t dst = st + SBH + (pl ? SB_LO_DELTA : 0) + row * BSTRIDE + q * 16;
            cp16(dst, src, 16);
        }
    };

    float r0[4], r1[4], r2[4];
    if (MODE == 1) {
#pragma unroll
        for (int t = 0; t < 4; t++) {
            const long p = m0 + (tid >> 3) + 32 * t;
            r0[t] = rel[p * 3 + 0];
            r1[t] = rel[p * 3 + 1];
            r2[t] = rel[p * 3 + 2];
        }
    }

    float acc[4][4][4];
#pragma unroll
    for (int i = 0; i < 4; i++)
#pragma unroll
        for (int j = 0; j < 4; j++)
#pragma unroll
            for (int r = 0; r < 4; r++) acc[i][j][r] = 0.f;

    const uint32_t aOff = (uint32_t)((warpM + (lane & 15)) * ASTRIDE + ((lane >> 4) << 4));
    const uint32_t bOff = (uint32_t)(((lane & 7) + ((lane >> 3) & 1) * 8) * BSTRIDE +
                                     (warpN + ((lane >> 4) << 3)) * 2);

    // prologue: NSTG-1 committed groups
#pragma unroll
    for (int t = 0; t < NSTG - 1; t++) {
        if (t < nc) issue_chunk(t);
        cp_commit();
    }

    for (int c = 0; c < nc; c++) {
        const uint32_t st = sb + (uint32_t)(c % NSTG) * STB;

        __syncthreads();                  // MMAs touching this stage complete
        if (c + NSTG - 1 < nc) issue_chunk(c + NSTG - 1);
        cp_commit();

        if (MODE == 1) {
            // build A(c) = fp16(relu(Anode + rel·W0c)) directly in SMEM
            const int c4 = tid & 7;
            const int k0 = c << 5;
            const float4 w0 = *(const float4*)(W0c3 + 0   + k0 + c4 * 4);
            const float4 w1 = *(const float4*)(W0c3 + 256 + k0 + c4 * 4);
            const float4 w2 = *(const float4*)(W0c3 + 512 + k0 + c4 * 4);
#pragma unroll
            for (int t = 0; t < 4; t++) {
                const int row = (tid >> 3) + 32 * t;
                const long node = (m0 + row) >> 3;
                const float4 a = *(const float4*)(Anode + node * 256 + k0 + c4 * 4);
                float4 o;
                o.x = fmaxf(a.x + r0[t] * w0.x + r1[t] * w1.x + r2[t] * w2.x, 0.f);
                o.y = fmaxf(a.y + r0[t] * w0.y + r1[t] * w1.y + r2[t] * w2.y, 0.f);
                o.z = fmaxf(a.z + r0[t] * w0.z + r1[t] * w1.z + r2[t] * w2.z, 0.f);
                o.w = fmaxf(a.w + r0[t] * w0.w + r1[t] * w1.w + r2[t] * w2.w, 0.f);
                uint2 hp;
                hp.x = pack2h(__float2half_rn(o.x), __float2half_rn(o.y));
                hp.y = pack2h(__float2half_rn(o.z), __float2half_rn(o.w));
                const int off = row * ASTRIDE + c4 * 8;
                *(uint2*)(smem + (st - sb) + SA_HI + off) = hp;
            }
        }

        cp_wait<NSTG - 1>();              // chunk c's cp.async data arrived
        __syncthreads();                  // ...and is visible to all threads

        const uint32_t aAddr = st + aOff;
        const uint32_t bAddr = st + SBH + bOff;

#pragma unroll
        for (int ks = 0; ks < 2; ks++) {
            uint32_t ah[4][4], bh[8], bl[8];
#pragma unroll
            for (int mi = 0; mi < 4; mi++)
                ldm_x4(ah[mi], aAddr + SA_HI + (uint32_t)(mi * 16 * ASTRIDE + ks * 32));
#pragma unroll
            for (int j = 0; j < 2; j++) {
                const uint32_t bo = bAddr + (uint32_t)(ks * 16 * BSTRIDE + j * 32);
                ldm_x4t(bh + j * 4, bo);
                ldm_x4t(bl + j * 4, bo + SB_LO_DELTA);
            }
#pragma unroll
            for (int mi = 0; mi < 4; mi++)
#pragma unroll
                for (int nj = 0; nj < 4; nj++) {
                    if (IS16) {
                        mma16816h(acc[mi][nj], ah[mi], bh + nj * 2);
                        mma16816h(acc[mi][nj], ah[mi], bl + nj * 2);
                    } else {
                        mma16816(acc[mi][nj], ah[mi], bh + nj * 2);
                        mma16816(acc[mi][nj], ah[mi], bl + nj * 2);
                    }
                }
            if (!IS16) {
                uint32_t al[4][4];
#pragma unroll
                for (int mi = 0; mi < 4; mi++)
                    ldm_x4(al[mi], aAddr + SA_LO_B + (uint32_t)(mi * 16 * ASTRIDE + ks * 32));
#pragma unroll
                for (int mi = 0; mi < 4; mi++)
#pragma unroll
                    for (int nj = 0; nj < 4; nj++)
                        mma16816(acc[mi][nj], al[mi], bh + nj * 2);
            }
        }
    }

    // ---- epilogue ----
    const long gmBase = m0 + warpM + (lane >> 2);
    const int  gcBase = n0 + warpN + (lane & 3) * 2;
#pragma unroll
    for (int mi = 0; mi < 4; mi++) {
#pragma unroll
        for (int half = 0; half < 2; half++) {
            const long gr = gmBase + mi * 16 + half * 8;
            if (gr >= M) continue;
#pragma unroll
            for (int nj = 0; nj < 4; nj++) {
                const int gc = gcBase + nj * 8;
                if (gc >= realN) continue;
                float vx = acc[mi][nj][half * 2 + 0];
                float vy = acc[mi][nj][half * 2 + 1];
                if (NSPLIT != 0 && gc >= NSPLIT) {
                    const int c2 = gc - NSPLIT;
                    vx += bias2[c2]; vy += bias2[c2 + 1];
                    float2 o; o.x = vx; o.y = vy;
                    *(float2*)(OutF + gr * (long)ldc + c2) = o;
                } else {
                    if (bias) { vx += bias[gc]; vy += bias[gc + 1]; }
                    if (Cin) {
                        const float2 cv = *(const float2*)(Cin + gr * (long)ldc + gc);
                        vx += cv.x; vy += cv.y;
                    }
                    if (doRelu) { vx = fmaxf(vx, 0.f); vy = fmaxf(vy, 0.f); }
                    if (OutHi) {
                        if (IS16) {
                            *(uint32_t*)(OutHi + gr * (long)ldc + gc) =
                                pack2h(__float2half_rn(vx), __float2half_rn(vy));
                        } else {
                            const __nv_bfloat16 hx = __float2bfloat16(vx);
                            const __nv_bfloat16 hy = __float2bfloat16(vy);
                            *(uint32_t*)(OutHi + gr * (long)ldc + gc) = pack2(hx, hy);
                            *(uint32_t*)(OutLo + gr * (long)ldc + gc) =
                                pack2(__float2bfloat16(vx - __bfloat162float(hx)),
                                      __float2bfloat16(vy - __bfloat162float(hy)));
                        }
                    } else {
                        float2 o; o.x = vx; o.y = vy;
                        *(float2*)(OutF + gr * (long)ldc + gc) = o;
                    }
                }
            }
        }
    }
}

// ---------------------------------------------------------------------------
__global__ __launch_bounds__(256)
void prep_weight(const float* __restrict__ W, unsigned short* __restrict__ hi,
                 unsigned short* __restrict__ lo, int K, int N,
                 int Kpad, int Nsub, int NpStride, int colOff)
{
    const int i = blockIdx.x * blockDim.x + threadIdx.x;
    if (i >= Kpad * Nsub) return;
    const int k = i / Nsub, n = i % Nsub;
    const float v = (k < K && n < N) ? W[(long)k * N + n] : 0.f;
    const __nv_bfloat16 h = __float2bfloat16(v);
    const int dst = k * NpStride + colOff + n;
    hi[dst] = __bfloat16_as_ushort(h);
    lo[dst] = __bfloat16_as_ushort(__float2bfloat16(v - __bfloat162float(h)));
}

__global__ __launch_bounds__(256)
void prep_weight_h(const float* __restrict__ W, unsigned short* __restrict__ hi,
                   unsigned short* __restrict__ lo, int K, int N,
                   int Kpad, int Nsub, int NpStride, int colOff)
{
    const int i = blockIdx.x * blockDim.x + threadIdx.x;
    if (i >= Kpad * Nsub) return;
    const int k = i / Nsub, n = i % Nsub;
    const float v = (k < K && n < N) ? W[(long)k * N + n] : 0.f;
    const __half h = __float2half_rn(v);
    const int dst = k * NpStride + colOff + n;
    hi[dst] = __half_as_ushort(h);
    lo[dst] = __half_as_ushort(__float2half_rn(v - __half2float(h)));
}

__global__ __launch_bounds__(256)
void split_x(const float* __restrict__ X, unsigned short* __restrict__ hi,
             unsigned short* __restrict__ lo)
{
    const long i = (long)blockIdx.x * blockDim.x + threadIdx.x;
    if (i >= (long)N_NODES * 64) return;
    const float4 v = *(const float4*)(X + i * 4);
    const __nv_bfloat16 hx = __float2bfloat16(v.x), hy = __float2bfloat16(v.y);
    const __nv_bfloat16 hz = __float2bfloat16(v.z), hw = __float2bfloat16(v.w);
    uint2 hp, lp;
    hp.x = pack2(hx, hy); hp.y = pack2(hz, hw);
    lp.x = pack2(__float2bfloat16(v.x - __bfloat162float(hx)),
                 __float2bfloat16(v.y - __bfloat162float(hy)));
    lp.y = pack2(__float2bfloat16(v.z - __bfloat162float(hz)),
                 __float2bfloat16(v.w - __bfloat162float(hw)));
    *(uint2*)(hi + i * 4) = hp;
    *(uint2*)(lo + i * 4) = lp;
}

__global__ __launch_bounds__(256)
void cluster_kernel(float* __restrict__ out)
{
    const int i = blockIdx.x * blockDim.x + threadIdx.x;
    if (i < M_PTS) out[i] = (float)(i >> 3);
}

// ---------------------------------------------------------------------------
extern "C" void kernel_launch(void* const* d_in, const int* in_sizes, int n_in,
                              void* d_out, int out_size)
{
    const float* X    = (const float*)d_in[0];
    const float* Wg0  = (const float*)d_in[1];
    const float* bg0  = (const float*)d_in[2];
    const float* Wg1  = (const float*)d_in[3];
    const float* bg1  = (const float*)d_in[4];
    const float* Wg2  = (const float*)d_in[5];
    const float* bg2  = (const float*)d_in[6];
    const float* Wdec = (const float*)d_in[7];
    const float* bdec = (const float*)d_in[8];
    const float* W0   = (const float*)d_in[9];
    const float* b0   = (const float*)d_in[10];
    const float* W1   = (const float*)d_in[11];
    const float* b1   = (const float*)d_in[12];
    const float* W2   = (const float*)d_in[13];
    const float* b2   = (const float*)d_in[14];

    float* out = (float*)d_out;
    float* out_rel     = out;
    float* out_decoded = out + 1200000;
    float* out_cluster = out + 1200000 + 102400000;

    float *T, *Abuf;
    unsigned short *whi, *wlo, *xhi, *xlo, *h1hi, *h1lo, *h2hi, *h2lo;
    unsigned short *fhi, *flo, *p1hi;
    cudaGetSymbolAddress((void**)&T,    g_T);
    cudaGetSymbolAddress((void**)&Abuf, g_A);
    cudaGetSymbolAddress((void**)&whi,  g_whi);
    cudaGetSymbolAddress((void**)&wlo,  g_wlo);
    cudaGetSymbolAddress((void**)&xhi,  g_xhi);
    cudaGetSymbolAddress((void**)&xlo,  g_xlo);
    cudaGetSymbolAddress((void**)&h1hi, g_h1hi);
    cudaGetSymbolAddress((void**)&h1lo, g_h1lo);
    cudaGetSymbolAddress((void**)&h2hi, g_h2hi);
    cudaGetSymbolAddress((void**)&h2lo, g_h2lo);
    cudaGetSymbolAddress((void**)&fhi,  g_fhi);
    cudaGetSymbolAddress((void**)&flo,  g_flo);
    cudaGetSymbolAddress((void**)&p1hi, g_p1hi);

    cudaFuncSetAttribute((const void*)gemm_mma<0,0,0>,   cudaFuncAttributeMaxDynamicSharedMemorySize, SMEM_DYN_B);
    cudaFuncSetAttribute((const void*)gemm_mma<0,256,0>, cudaFuncAttributeMaxDynamicSharedMemorySize, SMEM_DYN_B);
    cudaFuncSetAttribute((const void*)gemm_mma<1,0,1>,   cudaFuncAttributeMaxDynamicSharedMemorySize, SMEM_DYN_H);
    cudaFuncSetAttribute((const void*)gemm_mma<0,0,1>,   cudaFuncAttributeMaxDynamicSharedMemorySize, SMEM_DYN_H);

    const float* W0a = W0;
    const float* W0b = W0 + 256 * 256;
    const float* W0c = W0 + 320 * 256;

    auto prep = [&](const float* W, int off, int K, int N, int Kp, int Nsub,
                    int stride, int colOff) {
        const int total = Kp * Nsub;
        prep_weight<<<(total + 255) / 256, 256>>>(W, whi + off, wlo + off,
                                                  K, N, Kp, Nsub, stride, colOff);
    };
    prep(Wg0,  OFF_WG0A, 256, 256, 256, 256, 512, 0);
    prep(W0a,  OFF_WG0A, 256, 256, 256, 256, 512, 256);
    prep(Wg1,  OFF_WG1,  256, 128, 256, 128, 128, 0);
    prep(Wg2,  OFF_WG2,  128,  64, 128, 128, 128, 0);
    prep(Wdec, OFF_WDEC,  64,  24,  64, 128, 128, 0);
    prep(W0b,  OFF_W0B,   64, 256,  64, 256, 256, 0);
    prep_weight_h<<<(256 * 256 + 255) / 256, 256>>>(W1, whi + OFF_W1, wlo + OFF_W1,
                                                    256, 256, 256, 256, 256, 0);
    prep_weight_h<<<(256 * 256 + 255) / 256, 256>>>(W2, whi + OFF_W2, wlo + OFF_W2,
                                                    256, 256, 256, 256, 256, 0);

    split_x<<<(N_NODES * 64 + 255) / 256, 256>>>(X, xhi, xlo);

    auto gemm0 = [&](const unsigned short* Ahi, const unsigned short* Alo, int off,
                     const float* bias, const float* Cin,
                     float* OutF, unsigned short* OutHi, unsigned short* OutLo,
                     int M, int K, int Np, int realN, int ldc, int relu) {
        dim3 grid((realN + 127) / 128, (M + 127) / 128);
        gemm_mma<0,0,0><<<grid, 256, SMEM_DYN_B>>>(Ahi, Alo, whi + off, wlo + off,
                                                   bias, nullptr, Cin,
                                                   nullptr, nullptr, nullptr,
                                                   OutF, OutHi, OutLo,
                                                   M, K, Np, realN, ldc, relu);
    };

    // fused: h1 = relu(X@Wg0+bg0) (cols 0-255, planes); T = X@W0a+b0 (cols 256-511, fp32)
    {
        dim3 grid(4, (N_NODES + 127) / 128);
        gemm_mma<0,256,0><<<grid, 256, SMEM_DYN_B>>>(xhi, xlo, whi + OFF_WG0A, wlo + OFF_WG0A,
                                                     bg0, b0, nullptr,
                                                     nullptr, nullptr, nullptr,
                                                     T, h1hi, h1lo,
                                                     N_NODES, 256, 512, 512, 256, 1);
    }
    // global MLP tail
    gemm0(h1hi, h1lo, OFF_WG1, bg1, nullptr, nullptr, h2hi, h2lo,
          N_NODES, 256, 128, 128, 128, 1);
    gemm0(h2hi, h2lo, OFF_WG2, bg2, nullptr, nullptr, fhi, flo,
          N_NODES, 128, 128, 64, 64, 1);
    // decoder head -> relative_points (fp32 into d_out)
    gemm0(fhi, flo, OFF_WDEC, bdec, nullptr, out_rel, nullptr, nullptr,
          N_NODES, 64, 128, 24, 24, 0);
    // Abuf = T + feats@W0b (fp32)
    gemm0(fhi, flo, OFF_W0B, nullptr, T, Abuf, nullptr, nullptr,
          N_NODES, 64, 256, 256, 256, 0);
    // point-MLP layer 1: fused h0 build, fp16 2-term, 3-stage -> p1 fp16 plane
    {
        dim3 grid(2, M_PTS / 128);
        gemm_mma<1,0,1><<<grid, 256, SMEM_DYN_H>>>(nullptr, nullptr,
                                                   whi + OFF_W1, wlo + OFF_W1,
                                                   b1, nullptr, nullptr,
                                                   Abuf, out_rel, W0c,
                                                   nullptr, p1hi, nullptr,
                                                   M_PTS, 256, 256, 256, 256, 1);
    }
    // point-MLP layer 2: fp16 2-term, 3-stage -> decoded output (fp32)
    {
        dim3 grid(2, M_PTS / 128);
        gemm_mma<0,0,1><<<grid, 256, SMEM_DYN_H>>>(p1hi, nullptr,
                                                   whi + OFF_W2, wlo + OFF_W2,
                                                   b2, nullptr, nullptr,
                                                   nullptr, nullptr, nullptr,
                                                   out_decoded, nullptr, nullptr,
                                                   M_PTS, 256, 256, 256, 256, 1);
    }
    // cluster ids
    cluster_kernel<<<(M_PTS + 255) / 256, 256>>>(out_cluster);
}

// round 16
// speedup vs baseline: 1.0986x; 1.0986x over previous
#include <cuda_runtime.h>
#include <cuda_bf16.h>
#include <cuda_fp16.h>
#include <cstdint>

// ---------------------------------------------------------------------------
// MiddleLayerDecoder — round 15: R12 base (K32, 2-stage, 2 CTAs/SM) with the
// fp16 arm's B operand moved out of SMEM: W1/W2 pre-packed in fragment-major
// layout, loaded per-ks with direct coalesced LDG.128 (L1-resident weights).
// bf16 node arm byte-identical to R12.
// ---------------------------------------------------------------------------

#define N_NODES 50000
#define KPTS 8
#define M_PTS (N_NODES * KPTS)

// ---- activation planes ----
__device__ __align__(16) __nv_bfloat16 g_xhi[(size_t)N_NODES * 256];
__device__ __align__(16) __nv_bfloat16 g_xlo[(size_t)N_NODES * 256];
__device__ __align__(16) __nv_bfloat16 g_h1hi[(size_t)N_NODES * 256];
__device__ __align__(16) __nv_bfloat16 g_h1lo[(size_t)N_NODES * 256];
__device__ __align__(16) __nv_bfloat16 g_h2hi[(size_t)N_NODES * 128];
__device__ __align__(16) __nv_bfloat16 g_h2lo[(size_t)N_NODES * 128];
__device__ __align__(16) __nv_bfloat16 g_fhi[(size_t)N_NODES * 64];
__device__ __align__(16) __nv_bfloat16 g_flo[(size_t)N_NODES * 64];
__device__ __align__(16) unsigned short g_p1hi[(size_t)M_PTS * 256];  // fp16 plane
// fp32 scratch
__device__ float g_T[(size_t)N_NODES * 256];
__device__ float g_A[(size_t)N_NODES * 256];
// weight planes pool (bf16 bits) for the node arm
__device__ __align__(16) unsigned short g_whi[335872];
__device__ __align__(16) unsigned short g_wlo[335872];
// fragment-major fp16 weights for the big GEMMs (hi+lo interleaved by plane)
__device__ __align__(16) uint32_t g_w1frag[65536];
__device__ __align__(16) uint32_t g_w2frag[65536];

// pool map (bf16 arm)
#define OFF_WG0A 0        // 256 x 512 (Wg0 | W0a)
#define OFF_WG1  131072   // 256 x 128
#define OFF_WG2  163840   // 128 x 128
#define OFF_WDEC 180224   //  64 x 128
#define OFF_W0B  188416   //  64 x 256

__device__ __forceinline__ uint32_t smem_u32(const void* p) {
    uint32_t a;
    asm("{ .reg .u64 t; cvta.to.shared.u64 t, %1; cvt.u32.u64 %0, t; }" : "=r"(a) : "l"(p));
    return a;
}
__device__ __forceinline__ uint32_t pack2(__nv_bfloat16 a, __nv_bfloat16 b) {
    return (uint32_t)__bfloat16_as_ushort(a) | ((uint32_t)__bfloat16_as_ushort(b) << 16);
}
__device__ __forceinline__ uint32_t pack2h(__half a, __half b) {
    return (uint32_t)__half_as_ushort(a) | ((uint32_t)__half_as_ushort(b) << 16);
}
__device__ __forceinline__ void ldm_x4(uint32_t* r, uint32_t addr) {
    asm volatile("ldmatrix.sync.aligned.m8n8.x4.shared.b16 {%0,%1,%2,%3}, [%4];"
                 : "=r"(r[0]), "=r"(r[1]), "=r"(r[2]), "=r"(r[3]) : "r"(addr));
}
__device__ __forceinline__ void ldm_x4t(uint32_t* r, uint32_t addr) {
    asm volatile("ldmatrix.sync.aligned.m8n8.x4.trans.shared.b16 {%0,%1,%2,%3}, [%4];"
                 : "=r"(r[0]), "=r"(r[1]), "=r"(r[2]), "=r"(r[3]) : "r"(addr));
}
__device__ __forceinline__ void mma16816(float* c, const uint32_t* a, const uint32_t* b) {
    asm volatile("mma.sync.aligned.m16n8k16.row.col.f32.bf16.bf16.f32 "
                 "{%0,%1,%2,%3}, {%4,%5,%6,%7}, {%8,%9}, {%0,%1,%2,%3};"
                 : "+f"(c[0]), "+f"(c[1]), "+f"(c[2]), "+f"(c[3])
                 : "r"(a[0]), "r"(a[1]), "r"(a[2]), "r"(a[3]), "r"(b[0]), "r"(b[1]));
}
__device__ __forceinline__ void mma16816h(float* c, const uint32_t* a, const uint32_t* b) {
    asm volatile("mma.sync.aligned.m16n8k16.row.col.f32.f16.f16.f32 "
                 "{%0,%1,%2,%3}, {%4,%5,%6,%7}, {%8,%9}, {%0,%1,%2,%3};"
                 : "+f"(c[0]), "+f"(c[1]), "+f"(c[2]), "+f"(c[3])
                 : "r"(a[0]), "r"(a[1]), "r"(a[2]), "r"(a[3]), "r"(b[0]), "r"(b[1]));
}
__device__ __forceinline__ void cp16(uint32_t dst, const void* src, int sz) {
    asm volatile("cp.async.cg.shared.global [%0], [%1], 16, %2;"
                 :: "r"(dst), "l"(src), "r"(sz) : "memory");
}
__device__ __forceinline__ void cp_commit() {
    asm volatile("cp.async.commit_group;" ::: "memory");
}
__device__ __forceinline__ void cp_wait1() {
    asm volatile("cp.async.wait_group 1;" ::: "memory");
}

// stage layouts (K32 chunks, both arms)
#define ASTRIDE 80
#define BSTRIDE 272
#define SA_HI 0
// bf16 arm (3-term): A hi/lo + B hi/lo in SMEM
#define SA_LO_B 10240
#define SB_HI_B 20480
#define SB_LO_DELTA 8704
#define STAGE_B 37888
// fp16 arm (2-term): A only in SMEM (B via LDG fragments)
#define STAGE_H 10240
#define SMEM_DYN_B (STAGE_B * 2)
#define SMEM_DYN_H (STAGE_H * 2)

// MODE 0: A from pre-split planes (cp.async); MODE 1: A built on the fly (h0)
// NSPLIT>0: cols >= NSPLIT -> OutF fp32 + bias2, no relu
// IS16: fp16 2-term, B via fragment-major LDG; else bf16 3-term via SMEM
template <int MODE, int NSPLIT, int IS16>
__global__ __launch_bounds__(256, 2)
void gemm_mma(const unsigned short* __restrict__ Ahi,
              const unsigned short* __restrict__ Alo,
              const unsigned short* __restrict__ Bhi,
              const unsigned short* __restrict__ Blo,
              const uint32_t* __restrict__ Bfrag,
              const float* __restrict__ bias, const float* __restrict__ bias2,
              const float* __restrict__ Cin,
              const float* __restrict__ Anode, const float* __restrict__ rel,
              const float* __restrict__ W0c3,
              float* __restrict__ OutF,
              unsigned short* __restrict__ OutHi, unsigned short* __restrict__ OutLo,
              int M, int K, int Np, int realN, int ldc, int doRelu)
{
    constexpr uint32_t STB = IS16 ? STAGE_H : STAGE_B;

    extern __shared__ __align__(128) char smem[];
    const uint32_t sb = smem_u32(smem);
    const int tid = threadIdx.x, lane = tid & 31, wid = tid >> 5;
    const int warpM = (wid & 1) * 64;
    const int warpN = (wid >> 1) * 32;
    const long m0 = (long)blockIdx.y * 128;
    const int  n0 = blockIdx.x * 128;
    const int  nc = K >> 5;

    auto issue_chunk = [&](int c) {
        const uint32_t st = sb + (uint32_t)(c & 1) * STB;
        const int k0 = c << 5;
        if (MODE == 0) {
            if (IS16) {
                // A hi plane only: 512 granules
#pragma unroll
                for (int t = 0; t < 2; t++) {
                    const int gi = tid + t * 256;
                    const int row = gi >> 2, q = gi & 3;
                    const long gm = m0 + row;
                    const unsigned short* src =
                        Ahi + (gm < M ? gm : 0) * (long)K + k0 + q * 8;
                    cp16(st + SA_HI + row * ASTRIDE + q * 16, src, gm < M ? 16 : 0);
                }
            } else {
#pragma unroll
                for (int t = 0; t < 4; t++) {
                    const int gi = tid + t * 256;
                    const int pl = gi >> 9, idx = gi & 511;
                    const int row = idx >> 2, q = idx & 3;
                    const long gm = m0 + row;
                    const unsigned short* src =
                        (pl ? Alo : Ahi) + (gm < M ? gm : 0) * (long)K + k0 + q * 8;
                    cp16(st + (pl ? SA_LO_B : SA_HI) + row * ASTRIDE + q * 16, src,
                         gm < M ? 16 : 0);
                }
            }
        }
        if (!IS16) {
#pragma unroll
            for (int t = 0; t < 4; t++) {
                const int gi = tid + t * 256;
                const int pl = gi >> 9, idx = gi & 511;
                const int row = idx >> 4, q = idx & 15;
                const unsigned short* src =
                    (pl ? Blo : Bhi) + (long)(k0 + row) * Np + n0 + q * 8;
                cp16(st + SB_HI_B + (pl ? SB_LO_DELTA : 0) + row * BSTRIDE + q * 16,
                     src, 16);
            }
        }
    };

    float r0[4], r1[4], r2[4];
    if (MODE == 1) {
#pragma unroll
        for (int t = 0; t < 4; t++) {
            const long p = m0 + (tid >> 3) + 32 * t;
            r0[t] = rel[p * 3 + 0];
            r1[t] = rel[p * 3 + 1];
            r2[t] = rel[p * 3 + 2];
        }
    }

    float acc[4][4][4];
#pragma unroll
    for (int i = 0; i < 4; i++)
#pragma unroll
        for (int j = 0; j < 4; j++)
#pragma unroll
            for (int r = 0; r < 4; r++) acc[i][j][r] = 0.f;

    const uint32_t aOff = (uint32_t)((warpM + (lane & 15)) * ASTRIDE + ((lane >> 4) << 4));
    const uint32_t bOff = (uint32_t)(((lane & 7) + ((lane >> 3) & 1) * 8) * BSTRIDE +
                                     (warpN + ((lane >> 4) << 3)) * 2);
    // fragment-major B base for this warp (IS16): global nblk = blockIdx.x*4 + wid>>1
    const uint32_t* pwBase =
        IS16 ? (Bfrag + (uint32_t)(blockIdx.x * 4 + (wid >> 1)) * 1024 + lane * 4)
             : nullptr;

    const bool hasCp = (MODE == 0) || !IS16;
    if (hasCp) { issue_chunk(0); cp_commit(); }

    for (int c = 0; c < nc; c++) {
        const uint32_t st = sb + (uint32_t)(c & 1) * STB;

        __syncthreads();                  // MMAs of c-1 complete everywhere
        if (hasCp) {
            if (c + 1 < nc) issue_chunk(c + 1);
            cp_commit();
        }

        if (MODE == 1) {
            // build A(c) = fp16(relu(Anode + rel·W0c)) directly in SMEM
            const int c4 = tid & 7;
            const int k0 = c << 5;
            const float4 w0 = *(const float4*)(W0c3 + 0   + k0 + c4 * 4);
            const float4 w1 = *(const float4*)(W0c3 + 256 + k0 + c4 * 4);
            const float4 w2 = *(const float4*)(W0c3 + 512 + k0 + c4 * 4);
#pragma unroll
            for (int t = 0; t < 4; t++) {
                const int row = (tid >> 3) + 32 * t;
                const long node = (m0 + row) >> 3;
                const float4 a = *(const float4*)(Anode + node * 256 + k0 + c4 * 4);
                float4 o;
                o.x = fmaxf(a.x + r0[t] * w0.x + r1[t] * w1.x + r2[t] * w2.x, 0.f);
                o.y = fmaxf(a.y + r0[t] * w0.y + r1[t] * w1.y + r2[t] * w2.y, 0.f);
                o.z = fmaxf(a.z + r0[t] * w0.z + r1[t] * w1.z + r2[t] * w2.z, 0.f);
                o.w = fmaxf(a.w + r0[t] * w0.w + r1[t] * w1.w + r2[t] * w2.w, 0.f);
                uint2 hp;
                hp.x = pack2h(__float2half_rn(o.x), __float2half_rn(o.y));
                hp.y = pack2h(__float2half_rn(o.z), __float2half_rn(o.w));
                const int off = row * ASTRIDE + c4 * 8;
                *(uint2*)(smem + (st - sb) + SA_HI + off) = hp;
            }
        }

        if (hasCp) cp_wait1();            // chunk c's cp.async data arrived
        __syncthreads();                  // ...and A-build/loads visible to all

        const uint32_t aAddr = st + aOff;
        const uint32_t bAddr = st + SB_HI_B + bOff;
        const uint32_t* pwc = IS16 ? (pwBase + c * 8192) : nullptr;

#pragma unroll
        for (int ks = 0; ks < 2; ks++) {
            uint32_t ah[4][4];
#pragma unroll
            for (int mi = 0; mi < 4; mi++)
                ldm_x4(ah[mi], aAddr + SA_HI + (uint32_t)(mi * 16 * ASTRIDE + ks * 32));

            if (IS16) {
                uint4 bhv[2], blv[2];
                bhv[0] = *(const uint4*)(pwc + (2 * ks + 0) * 128);
                bhv[1] = *(const uint4*)(pwc + (2 * ks + 1) * 128);
                blv[0] = *(const uint4*)(pwc + 512 + (2 * ks + 0) * 128);
                blv[1] = *(const uint4*)(pwc + 512 + (2 * ks + 1) * 128);
                const uint32_t* bh = (const uint32_t*)bhv;
                const uint32_t* bl = (const uint32_t*)blv;
#pragma unroll
                for (int mi = 0; mi < 4; mi++)
#pragma unroll
                    for (int nj = 0; nj < 4; nj++) {
                        mma16816h(acc[mi][nj], ah[mi], bh + nj * 2);
                        mma16816h(acc[mi][nj], ah[mi], bl + nj * 2);
                    }
            } else {
                uint32_t bh[8], bl[8];
#pragma unroll
                for (int j = 0; j < 2; j++) {
                    const uint32_t bo = bAddr + (uint32_t)(ks * 16 * BSTRIDE + j * 32);
                    ldm_x4t(bh + j * 4, bo);
                    ldm_x4t(bl + j * 4, bo + SB_LO_DELTA);
                }
#pragma unroll
                for (int mi = 0; mi < 4; mi++)
#pragma unroll
                    for (int nj = 0; nj < 4; nj++) {
                        mma16816(acc[mi][nj], ah[mi], bh + nj * 2);
                        mma16816(acc[mi][nj], ah[mi], bl + nj * 2);
                    }
                uint32_t al[4][4];
#pragma unroll
                for (int mi = 0; mi < 4; mi++)
                    ldm_x4(al[mi], aAddr + SA_LO_B + (uint32_t)(mi * 16 * ASTRIDE + ks * 32));
#pragma unroll
                for (int mi = 0; mi < 4; mi++)
#pragma unroll
                    for (int nj = 0; nj < 4; nj++)
                        mma16816(acc[mi][nj], al[mi], bh + nj * 2);
            }
        }
    }

    // ---- epilogue ----
    const long gmBase = m0 + warpM + (lane >> 2);
    const int  gcBase = n0 + warpN + (lane & 3) * 2;
#pragma unroll
    for (int mi = 0; mi < 4; mi++) {
#pragma unroll
        for (int half = 0; half < 2; half++) {
            const long gr = gmBase + mi * 16 + half * 8;
            if (gr >= M) continue;
#pragma unroll
            for (int nj = 0; nj < 4; nj++) {
                const int gc = gcBase + nj * 8;
                if (gc >= realN) continue;
                float vx = acc[mi][nj][half * 2 + 0];
                float vy = acc[mi][nj][half * 2 + 1];
                if (NSPLIT != 0 && gc >= NSPLIT) {
                    const int c2 = gc - NSPLIT;
                    vx += bias2[c2]; vy += bias2[c2 + 1];
                    float2 o; o.x = vx; o.y = vy;
                    *(float2*)(OutF + gr * (long)ldc + c2) = o;
                } else {
                    if (bias) { vx += bias[gc]; vy += bias[gc + 1]; }
                    if (Cin) {
                        const float2 cv = *(const float2*)(Cin + gr * (long)ldc + gc);
                        vx += cv.x; vy += cv.y;
                    }
                    if (doRelu) { vx = fmaxf(vx, 0.f); vy = fmaxf(vy, 0.f); }
                    if (OutHi) {
                        if (IS16) {
                            *(uint32_t*)(OutHi + gr * (long)ldc + gc) =
                                pack2h(__float2half_rn(vx), __float2half_rn(vy));
                        } else {
                            const __nv_bfloat16 hx = __float2bfloat16(vx);
                            const __nv_bfloat16 hy = __float2bfloat16(vy);
                            *(uint32_t*)(OutHi + gr * (long)ldc + gc) = pack2(hx, hy);
                            *(uint32_t*)(OutLo + gr * (long)ldc + gc) =
                                pack2(__float2bfloat16(vx - __bfloat162float(hx)),
                                      __float2bfloat16(vy - __bfloat162float(hy)));
                        }
                    } else {
                        float2 o; o.x = vx; o.y = vy;
                        *(float2*)(OutF + gr * (long)ldc + gc) = o;
                    }
                }
            }
        }
    }
}

// ---------------------------------------------------------------------------
__global__ __launch_bounds__(256)
void prep_weight(const float* __restrict__ W, unsigned short* __restrict__ hi,
                 unsigned short* __restrict__ lo, int K, int N,
                 int Kpad, int Nsub, int NpStride, int colOff)
{
    const int i = blockIdx.x * blockDim.x + threadIdx.x;
    if (i >= Kpad * Nsub) return;
    const int k = i / Nsub, n = i % Nsub;
    const float v = (k < K && n < N) ? W[(long)k * N + n] : 0.f;
    const __nv_bfloat16 h = __float2bfloat16(v);
    const int dst = k * NpStride + colOff + n;
    hi[dst] = __bfloat16_as_ushort(h);
    lo[dst] = __bfloat16_as_ushort(__float2bfloat16(v - __bfloat162float(h)));
}

// fragment-major fp16 weight packer for W[256,256]:
// index bits: word 0-1 | lane 2-6 | g 7-8 | plane 9 | nblk 10-12 | c 13-15
__global__ __launch_bounds__(256)
void prep_wfrag(const float* __restrict__ W, uint32_t* __restrict__ out)
{
    const int i = blockIdx.x * blockDim.x + threadIdx.x;
    if (i >= 65536) return;
    const int word  = i & 3;
    const int lane  = (i >> 2) & 31;
    const int g     = (i >> 7) & 3;
    const int plane = (i >> 9) & 1;
    const int nblk  = (i >> 10) & 7;
    const int c     = (i >> 13);
    const int ridx = g * 4 + word;          // 0..15
    const int ks = ridx >> 3, nj = (ridx >> 1) & 3, r = ridx & 1;
    const int k = c * 32 + ks * 16 + r * 8 + 2 * (lane & 3);
    const int n = nblk * 32 + nj * 8 + (lane >> 2);
    const float v0 = W[(long)k * 256 + n];
    const float v1 = W[(long)(k + 1) * 256 + n];
    const __half h0 = __float2half_rn(v0), h1 = __float2half_rn(v1);
    uint32_t val;
    if (plane == 0)
        val = pack2h(h0, h1);
    else
        val = pack2h(__float2half_rn(v0 - __half2float(h0)),
                     __float2half_rn(v1 - __half2float(h1)));
    out[i] = val;
}

__global__ __launch_bounds__(256)
void split_x(const float* __restrict__ X, unsigned short* __restrict__ hi,
             unsigned short* __restrict__ lo)
{
    const long i = (long)blockIdx.x * blockDim.x + threadIdx.x;
    if (i >= (long)N_NODES * 64) return;
    const float4 v = *(const float4*)(X + i * 4);
    const __nv_bfloat16 hx = __float2bfloat16(v.x), hy = __float2bfloat16(v.y);
    const __nv_bfloat16 hz = __float2bfloat16(v.z), hw = __float2bfloat16(v.w);
    uint2 hp, lp;
    hp.x = pack2(hx, hy); hp.y = pack2(hz, hw);
    lp.x = pack2(__float2bfloat16(v.x - __bfloat162float(hx)),
                 __float2bfloat16(v.y - __bfloat162float(hy)));
    lp.y = pack2(__float2bfloat16(v.z - __bfloat162float(hz)),
                 __float2bfloat16(v.w - __bfloat162float(hw)));
    *(uint2*)(hi + i * 4) = hp;
    *(uint2*)(lo + i * 4) = lp;
}

__global__ __launch_bounds__(256)
void cluster_kernel(float* __restrict__ out)
{
    const int i = blockIdx.x * blockDim.x + threadIdx.x;
    if (i < M_PTS) out[i] = (float)(i >> 3);
}

// ---------------------------------------------------------------------------
extern "C" void kernel_launch(void* const* d_in, const int* in_sizes, int n_in,
                              void* d_out, int out_size)
{
    const float* X    = (const float*)d_in[0];
    const float* Wg0  = (const float*)d_in[1];
    const float* bg0  = (const float*)d_in[2];
    const float* Wg1  = (const float*)d_in[3];
    const float* bg1  = (const float*)d_in[4];
    const float* Wg2  = (const float*)d_in[5];
    const float* bg2  = (const float*)d_in[6];
    const float* Wdec = (const float*)d_in[7];
    const float* bdec = (const float*)d_in[8];
    const float* W0   = (const float*)d_in[9];
    const float* b0   = (const float*)d_in[10];
    const float* W1   = (const float*)d_in[11];
    const float* b1   = (const float*)d_in[12];
    const float* W2   = (const float*)d_in[13];
    const float* b2   = (const float*)d_in[14];

    float* out = (float*)d_out;
    float* out_rel     = out;
    float* out_decoded = out + 1200000;
    float* out_cluster = out + 1200000 + 102400000;

    float *T, *Abuf;
    unsigned short *whi, *wlo, *xhi, *xlo, *h1hi, *h1lo, *h2hi, *h2lo;
    unsigned short *fhi, *flo, *p1hi;
    uint32_t *w1f, *w2f;
    cudaGetSymbolAddress((void**)&T,    g_T);
    cudaGetSymbolAddress((void**)&Abuf, g_A);
    cudaGetSymbolAddress((void**)&whi,  g_whi);
    cudaGetSymbolAddress((void**)&wlo,  g_wlo);
    cudaGetSymbolAddress((void**)&xhi,  g_xhi);
    cudaGetSymbolAddress((void**)&xlo,  g_xlo);
    cudaGetSymbolAddress((void**)&h1hi, g_h1hi);
    cudaGetSymbolAddress((void**)&h1lo, g_h1lo);
    cudaGetSymbolAddress((void**)&h2hi, g_h2hi);
    cudaGetSymbolAddress((void**)&h2lo, g_h2lo);
    cudaGetSymbolAddress((void**)&fhi,  g_fhi);
    cudaGetSymbolAddress((void**)&flo,  g_flo);
    cudaGetSymbolAddress((void**)&p1hi, g_p1hi);
    cudaGetSymbolAddress((void**)&w1f,  g_w1frag);
    cudaGetSymbolAddress((void**)&w2f,  g_w2frag);

    cudaFuncSetAttribute((const void*)gemm_mma<0,0,0>,   cudaFuncAttributeMaxDynamicSharedMemorySize, SMEM_DYN_B);
    cudaFuncSetAttribute((const void*)gemm_mma<0,256,0>, cudaFuncAttributeMaxDynamicSharedMemorySize, SMEM_DYN_B);
    cudaFuncSetAttribute((const void*)gemm_mma<1,0,1>,   cudaFuncAttributeMaxDynamicSharedMemorySize, SMEM_DYN_H);
    cudaFuncSetAttribute((const void*)gemm_mma<0,0,1>,   cudaFuncAttributeMaxDynamicSharedMemorySize, SMEM_DYN_H);

    const float* W0a = W0;
    const float* W0b = W0 + 256 * 256;
    const float* W0c = W0 + 320 * 256;

    auto prep = [&](const float* W, int off, int K, int N, int Kp, int Nsub,
                    int stride, int colOff) {
        const int total = Kp * Nsub;
        prep_weight<<<(total + 255) / 256, 256>>>(W, whi + off, wlo + off,
                                                  K, N, Kp, Nsub, stride, colOff);
    };
    prep(Wg0,  OFF_WG0A, 256, 256, 256, 256, 512, 0);
    prep(W0a,  OFF_WG0A, 256, 256, 256, 256, 512, 256);
    prep(Wg1,  OFF_WG1,  256, 128, 256, 128, 128, 0);
    prep(Wg2,  OFF_WG2,  128,  64, 128, 128, 128, 0);
    prep(Wdec, OFF_WDEC,  64,  24,  64, 128, 128, 0);
    prep(W0b,  OFF_W0B,   64, 256,  64, 256, 256, 0);
    prep_wfrag<<<256, 256>>>(W1, w1f);
    prep_wfrag<<<256, 256>>>(W2, w2f);

    split_x<<<(N_NODES * 64 + 255) / 256, 256>>>(X, xhi, xlo);

    auto gemm0 = [&](const unsigned short* Ahi, const unsigned short* Alo, int off,
                     const float* bias, const float* Cin,
                     float* OutF, unsigned short* OutHi, unsigned short* OutLo,
                     int M, int K, int Np, int realN, int ldc, int relu) {
        dim3 grid((realN + 127) / 128, (M + 127) / 128);
        gemm_mma<0,0,0><<<grid, 256, SMEM_DYN_B>>>(Ahi, Alo, whi + off, wlo + off,
                                                   nullptr, bias, nullptr, Cin,
                                                   nullptr, nullptr, nullptr,
                                                   OutF, OutHi, OutLo,
                                                   M, K, Np, realN, ldc, relu);
    };

    // fused: h1 = relu(X@Wg0+bg0) (cols 0-255, planes); T = X@W0a+b0 (cols 256-511, fp32)
    {
        dim3 grid(4, (N_NODES + 127) / 128);
        gemm_mma<0,256,0><<<grid, 256, SMEM_DYN_B>>>(xhi, xlo, whi + OFF_WG0A, wlo + OFF_WG0A,
                                                     nullptr, bg0, b0, nullptr,
                                                     nullptr, nullptr, nullptr,
                                                     T, h1hi, h1lo,
                                                     N_NODES, 256, 512, 512, 256, 1);
    }
    // global MLP tail
    gemm0(h1hi, h1lo, OFF_WG1, bg1, nullptr, nullptr, h2hi, h2lo,
          N_NODES, 256, 128, 128, 128, 1);
    gemm0(h2hi, h2lo, OFF_WG2, bg2, nullptr, nullptr, fhi, flo,
          N_NODES, 128, 128, 64, 64, 1);
    // decoder head -> relative_points (fp32 into d_out)
    gemm0(fhi, flo, OFF_WDEC, bdec, nullptr, out_rel, nullptr, nullptr,
          N_NODES, 64, 128, 24, 24, 0);
    // Abuf = T + feats@W0b (fp32)
    gemm0(fhi, flo, OFF_W0B, nullptr, T, Abuf, nullptr, nullptr,
          N_NODES, 64, 256, 256, 256, 0);
    // point-MLP layer 1: fused h0 build, fp16 2-term, B via LDG fragments
    {
        dim3 grid(2, M_PTS / 128);
        gemm_mma<1,0,1><<<grid, 256, SMEM_DYN_H>>>(nullptr, nullptr, nullptr, nullptr,
                                                   w1f,
                                                   b1, nullptr, nullptr,
                                                   Abuf, out_rel, W0c,
                                                   nullptr, p1hi, nullptr,
                                                   M_PTS, 256, 256, 256, 256, 1);
    }
    // point-MLP layer 2: fp16 2-term, B via LDG fragments -> decoded (fp32)
    {
        dim3 grid(2, M_PTS / 128);
        gemm_mma<0,0,1><<<grid, 256, SMEM_DYN_H>>>(p1hi, nullptr, nullptr, nullptr,
                                                   w2f,
                                                   b2, nullptr, nullptr,
                                                   nullptr, nullptr, nullptr,
                                                   out_decoded, nullptr, nullptr,
                                                   M_PTS, 256, 256, 256, 256, 1);
    }
    // cluster ids
    cluster_kernel<<<(M_PTS + 255) / 256, 256>>>(out_cluster);
}